// round 16
// baseline (speedup 1.0000x reference)
#include <cuda_runtime.h>
#include <cuda_fp16.h>
#include <math.h>
#include <stdint.h>

// ---------------- problem constants ----------------
#define BATCH 2
#define CH    256
#define NH    4
#define DK    64          // CH / NH
#define HW_N  2304        // 48*48
#define C2    512         // 2*CH
#define C3    768         // 3*CH (q,k,v packed)
#define ZPARTS 72         // per-(m-tile, column-warp) partials

#define ESC 0.18033688011112042f   // 0.125 * log2(e)

// fused PV tile constants: m-tile 64, n-chunk 128, FA2-style register reuse
#define PVM 64
#define PVN 128
#define NCH (HW_N/PVN)    // 18
#define QROW 136          // q/v row stride (128 + 8 halves)
#define KROW 72           // k row stride (64 + 8 halves)
#define PV_SMEM ((2*64*QROW + 2*64*QROW + 64*KROW)*2)  // 78848 B

// ---------------- scratch (device globals) ----------
__device__ __half g_xs[BATCH*CH*HW_N];
__device__ __half g_ys[BATCH*CH*HW_N];
__device__ __half g_qkv[BATCH*C3*HW_N];           // rows 0-255 q, 256-511 k, 512-767 v  [b][c][n]
__device__ float  g_x2[BATCH*CH*HW_N];
__device__ float  g_y2[BATCH*CH*HW_N];
__device__ __half g_x2h[BATCH*CH*HW_N];
__device__ float  g_Z [BATCH*NH*HW_N];            // invZ
__device__ float  g_Zpart[ZPARTS*BATCH*NH*HW_N];  // per-(mtile,wx) partial row sums
__device__ __half g_wqkv1[C3*CH];
__device__ __half g_wqkv2[C3*CH];
__device__ float  g_qkvb1[C3];
__device__ float  g_qkvb2[C3];
__device__ float  g_pooled[BATCH*C2];
__device__ float  g_sescale[BATCH*C2];            // 1 + sigmoid(f)
__device__ float  g_gacc[BATCH*2*HW_N];           // gate pre-sigmoid accumulators

__device__ __forceinline__ float sigmoidf_(float v){ return 1.f/(1.f+expf(-v)); }

__device__ __forceinline__ float exp2_fast(float x)
{
    x = fminf(fmaxf(x, -60.f), 60.f);
    float m  = x + 12582912.0f;
    float rn = m - 12582912.0f;
    float r  = x - rn;
    int   iv = __float_as_int(m) - 0x4B400000;
    float p  = 0.0096181291f;
    p = fmaf(p, r, 0.0555041086f);
    p = fmaf(p, r, 0.2402265069f);
    p = fmaf(p, r, 0.6931471806f);
    p = fmaf(p, r, 1.0f);
    return p * __int_as_float((iv + 127) << 23);
}

__device__ __forceinline__ uint32_t smaddr(const void* p){
    return (uint32_t)__cvta_generic_to_shared(p);
}
__device__ __forceinline__ void cpa16(uint32_t dst, const void* src){
    asm volatile("cp.async.cg.shared.global [%0], [%1], 16;" :: "r"(dst), "l"(src));
}
__device__ __forceinline__ void cpa_commit(){
    asm volatile("cp.async.commit_group;" ::: "memory");
}
template<int N>
__device__ __forceinline__ void cpa_wait(){
    asm volatile("cp.async.wait_group %0;" :: "n"(N) : "memory");
}
__device__ __forceinline__ void ldm_x4(uint32_t &r0, uint32_t &r1, uint32_t &r2, uint32_t &r3,
                                       uint32_t a){
    asm volatile("ldmatrix.sync.aligned.m8n8.x4.shared.b16 {%0,%1,%2,%3}, [%4];"
        : "=r"(r0),"=r"(r1),"=r"(r2),"=r"(r3) : "r"(a));
}
__device__ __forceinline__ void ldm_x4t(uint32_t &r0, uint32_t &r1, uint32_t &r2, uint32_t &r3,
                                        uint32_t a){
    asm volatile("ldmatrix.sync.aligned.m8n8.x4.trans.shared.b16 {%0,%1,%2,%3}, [%4];"
        : "=r"(r0),"=r"(r1),"=r"(r2),"=r"(r3) : "r"(a));
}
__device__ __forceinline__ void mma_f16(float (&c)[4], uint32_t a0, uint32_t a1,
                                        uint32_t a2, uint32_t a3,
                                        uint32_t b0, uint32_t b1)
{
    asm volatile("mma.sync.aligned.m16n8k16.row.col.f32.f16.f16.f32 "
        "{%0,%1,%2,%3}, {%4,%5,%6,%7}, {%8,%9}, {%0,%1,%2,%3};"
        : "+f"(c[0]), "+f"(c[1]), "+f"(c[2]), "+f"(c[3])
        : "r"(a0), "r"(a1), "r"(a2), "r"(a3), "r"(b0), "r"(b1));
}
__device__ __forceinline__ uint32_t h2pack(float a, float b){
    __half2 h = __floats2half2_rn(a, b);
    return *reinterpret_cast<uint32_t*>(&h);
}

// ---- prep: qkv weight/bias pack (both rtrans) + gacc zero + channel pooling ----
__global__ void prep_kernel(const float* __restrict__ x, const float* __restrict__ y,
                            const float* __restrict__ qw1, const float* __restrict__ kw1,
                            const float* __restrict__ vw1,
                            const float* __restrict__ qb1, const float* __restrict__ kb1,
                            const float* __restrict__ vb1,
                            const float* __restrict__ qw2, const float* __restrict__ kw2,
                            const float* __restrict__ vw2,
                            const float* __restrict__ qb2, const float* __restrict__ kb2,
                            const float* __restrict__ vb2)
{
    int bid = blockIdx.x, t = threadIdx.x;
    if (bid < 1536){                                 // qkv weight pack: 2*768*256 elems
        int idx = bid*256 + t;
        int which = idx / (C3*CH);
        int li = idx % (C3*CH);
        int row = li / CH, col = li % CH;
        const float* w;
        int lr;
        if (row < CH)      { w = which ? qw2 : qw1; lr = row; }
        else if (row < C2) { w = which ? kw2 : kw1; lr = row - CH; }
        else               { w = which ? vw2 : vw1; lr = row - C2; }
        __half* dst = which ? g_wqkv2 : g_wqkv1;
        dst[li] = __float2half_rn(w[lr*CH + col]);
        if (li < C3){
            const float* bsrc;
            int br;
            if (li < CH)      { bsrc = which ? qb2 : qb1; br = li; }
            else if (li < C2) { bsrc = which ? kb2 : kb1; br = li - CH; }
            else              { bsrc = which ? vb2 : vb1; br = li - C2; }
            float* db = which ? g_qkvb2 : g_qkvb1;
            db[li] = bsrc[br];
        }
    } else if (bid == 1536){                         // zero gate accumulators
        for (int j = t; j < BATCH*2*HW_N; j += 256) g_gacc[j] = 0.f;
    } else {                                         // channel-mean pooling
        int idx = bid - 1537;                        // over BATCH*C2
        int b = idx / C2, ch = idx % C2;
        const float* src = (ch < CH) ? (x + ((long)b*CH + ch)*HW_N)
                                     : (y + ((long)b*CH + (ch-CH))*HW_N);
        float s = 0.f;
        for (int i = t; i < HW_N; i += 256) s += src[i];
        __shared__ float red[256];
        red[t] = s; __syncthreads();
        for (int st = 128; st > 0; st >>= 1){
            if (t < st) red[t] += red[t+st];
            __syncthreads();
        }
        if (t == 0) g_pooled[idx] = red[0] / (float)HW_N;
    }
}

// ---------------- SE MLP (tiny, 2 blocks) ----------------
__global__ void se_kernel(const float* __restrict__ w1, const float* __restrict__ b1,
                          const float* __restrict__ w2, const float* __restrict__ b2)
{
    int b = blockIdx.x, t = threadIdx.x;   // 512 threads
    __shared__ float sp[C2], sh[DK];
    sp[t] = g_pooled[b*C2 + t];
    __syncthreads();
    if (t < DK) {
        float s = b1[t];
        for (int c = 0; c < C2; c++) s += w1[t*C2 + c] * sp[c];
        sh[t] = fmaxf(s, 0.f);
    }
    __syncthreads();
    float f = b2[t];
    for (int j = 0; j < DK; j++) f += w2[t*DK + j] * sh[j];
    g_sescale[b*C2 + t] = 1.f + sigmoidf_(f);
}

// ---------------- elementwise SE scale (coalesced) ----------------
__global__ void scale_kernel(const float* __restrict__ x, const float* __restrict__ y)
{
    long i = (long)blockIdx.x*blockDim.x + threadIdx.x;
    if (i >= (long)BATCH*CH*HW_N) return;
    int b = (int)(i / (CH*HW_N));
    int c = (int)((i / HW_N) % CH);
    g_xs[i] = __float2half_rn(x[i] * g_sescale[b*C2 + c]);
    g_ys[i] = __float2half_rn(y[i] * g_sescale[b*C2 + CH + c]);
}

// invZ from ZPARTS partials
__global__ void zinv_kernel()
{
    int i = blockIdx.x*blockDim.x + threadIdx.x;
    if (i >= BATCH*NH*HW_N) return;
    float s = 0.f;
    #pragma unroll
    for (int p = 0; p < ZPARTS; p++) s += g_Zpart[(long)p*(BATCH*NH*HW_N) + i];
    g_Z[i] = 1.0f / s;
}

// ================= all-half cp.async tensor-core GEMM =================
// QLIM>0: B operand = (blockIdx.y < QLIM) ? Bq : B  (merged qkv conv)
// EXPZ: compute exp rowsums -> Zpart; ESTORE controls whether E is written
template<int BK, int ST, int BM, int BN, int WM, int WN,
         bool TRA, int BIAS, bool EXPZ, bool ESTORE, bool CHALF, int QLIM>
__global__ void __launch_bounds__(256)
hgemm(const __half* __restrict__ A, const __half* __restrict__ B,
      const __half* __restrict__ Bq,
      void* __restrict__ Cv,
      const float* __restrict__ bias, float* __restrict__ Zp,
      int K, int lda, int ldb, int ldc, int zdiv,
      long long sA1, long long sA2, long long sB1, long long sB2,
      long long sC1, long long sC2)
{
    constexpr int WCOLS = BN / WN;
    constexpr int MF = WM / 16;
    constexpr int NF = WN / 8;
    constexpr int PAD = 8;
    constexpr int A_CH = (BM*BK/8)/256;
    constexpr int B_CH = (BK*BN/8)/256;

    __shared__ __half As[ST][TRA ? BK : BM][(TRA ? BM : BK) + PAD];
    __shared__ __half Bs[ST][BK][BN + PAD];

    int z  = blockIdx.z;
    int z1 = z / zdiv, z2 = z - z1*zdiv;
    A += z1*sA1 + z2*sA2;
    if (QLIM > 0 && blockIdx.y < QLIM) B = Bq;
    B += z1*sB1 + z2*sB2;
    float*  Cf = CHALF ? nullptr : ((float*)Cv ? (float*)Cv + z1*sC1 + z2*sC2 : nullptr);
    __half* Ch = CHALF ? ((__half*)Cv + z1*sC1 + z2*sC2)
                       : ((EXPZ && ESTORE) ? ((__half*)Cv + z1*sC1 + z2*sC2) : nullptr);

    int bm = blockIdx.y*BM, bn = blockIdx.x*BN;

    int t    = threadIdx.x;
    int warp = t >> 5, lane = t & 31;
    int g = lane >> 2, t4 = lane & 3;
    int wy = warp / WCOLS, wx = warp % WCOLS;

    auto issue = [&](int s, int k0){
        #pragma unroll
        for (int i = 0; i < A_CH; i++){
            int idx = t + 256*i;
            if (TRA){
                int k = idx/(BM/8), m8 = idx%(BM/8);
                cpa16(smaddr(&As[s][k][m8*8]), &A[(long)(k0+k)*lda + bm + m8*8]);
            } else {
                int m = idx/(BK/8), k8 = idx%(BK/8);
                cpa16(smaddr(&As[s][m][k8*8]), &A[(long)(bm+m)*lda + k0 + k8*8]);
            }
        }
        #pragma unroll
        for (int i = 0; i < B_CH; i++){
            int idx = t + 256*i;
            int k = idx/(BN/8), n8 = idx%(BN/8);
            cpa16(smaddr(&Bs[s][k][n8*8]), &B[(long)(k0+k)*ldb + bn + n8*8]);
        }
        cpa_commit();
    };

    float acc[MF][NF][4] = {};

    int nT = K / BK;
    constexpr int PRE = (ST == 1) ? 1 : (ST - 1);
    #pragma unroll
    for (int s = 0; s < PRE; s++)
        if (s < nT) issue(s, s*BK);

    for (int tI = 0; tI < nT; tI++){
        if (ST >= 3 && tI < nT - (ST-2)) cpa_wait<(ST >= 3) ? ST-2 : 0>();
        else                             cpa_wait<0>();
        __syncthreads();
        if (ST > 1 && tI + ST-1 < nT) issue((tI + ST-1) % ST, (tI + ST-1)*BK);

        int cur = tI % ST;
        #pragma unroll
        for (int kc = 0; kc < BK/16; kc++){
            uint32_t af[MF][4]; uint32_t bf[NF][2];
            #pragma unroll
            for (int mf = 0; mf < MF; mf++){
                if (TRA){
                    uint32_t r0,r1,r2,r3;
                    uint32_t a = smaddr(&As[cur][kc*16 + (lane & 15)]
                                                [wy*WM + mf*16 + ((lane >> 4) << 3)]);
                    ldm_x4t(r0, r1, r2, r3, a);
                    af[mf][0]=r0; af[mf][1]=r2; af[mf][2]=r1; af[mf][3]=r3;
                } else {
                    uint32_t a = smaddr(&As[cur][wy*WM + mf*16 + (lane & 15)]
                                                [kc*16 + ((lane >> 4) << 3)]);
                    ldm_x4(af[mf][0], af[mf][1], af[mf][2], af[mf][3], a);
                }
            }
            #pragma unroll
            for (int nf2 = 0; nf2 < NF/2; nf2++){
                uint32_t a = smaddr(&Bs[cur][kc*16 + (lane & 15)]
                                            [wx*WN + nf2*16 + ((lane >> 4) << 3)]);
                ldm_x4t(bf[nf2*2][0], bf[nf2*2][1], bf[nf2*2+1][0], bf[nf2*2+1][1], a);
            }
            #pragma unroll
            for (int mf = 0; mf < MF; mf++)
                #pragma unroll
                for (int nf = 0; nf < NF; nf++)
                    mma_f16(acc[mf][nf], af[mf][0], af[mf][1], af[mf][2], af[mf][3],
                            bf[nf][0], bf[nf][1]);
        }
    }

    // ---------------- epilogue ----------------
    #pragma unroll
    for (int mf = 0; mf < MF; mf++){
        int rbase = bm + wy*WM + mf*16 + g;
        #pragma unroll
        for (int half = 0; half < 2; half++){
            int r = rbase + half*8;
            float bM = (BIAS == 1) ? bias[r] : 0.f;
            float rowsum = 0.f;
            #pragma unroll
            for (int nf = 0; nf < NF; nf++){
                int cI = bn + wx*WN + nf*8 + t4*2;
                float v0 = acc[mf][nf][half*2 + 0];
                float v1 = acc[mf][nf][half*2 + 1];
                if (EXPZ){
                    v0 = exp2_fast(v0*ESC);
                    v1 = exp2_fast(v1*ESC);
                    rowsum += v0 + v1;
                    if (ESTORE)
                        *reinterpret_cast<__half2*>(&Ch[(long)r*ldc + cI]) =
                            __floats2half2_rn(v0, v1);
                } else {
                    if (BIAS == 1){ v0 += bM; v1 += bM; }
                    if (CHALF){
                        *reinterpret_cast<__half2*>(&Ch[(long)r*ldc + cI]) =
                            __floats2half2_rn(v0, v1);
                    } else {
                        *reinterpret_cast<float2*>(&Cf[(long)r*ldc + cI]) = make_float2(v0, v1);
                    }
                }
            }
            if (EXPZ){
                rowsum += __shfl_xor_sync(0xffffffffu, rowsum, 1);
                rowsum += __shfl_xor_sync(0xffffffffu, rowsum, 2);
                if (t4 == 0)
                    Zp[((long)(blockIdx.x*WCOLS + wx)*(BATCH*NH) + z)*HW_N + r] = rowsum;
            }
        }
    }
}

// ========== fused recompute-S^T + PV, FA2-style register reuse ==========
// out^T[m][d] = sum_n E^T[m][n] * v^T[n][d];  E^T = exp2(S^T*ESC)*invZ[n]
// grid: (HW_N/PVM, 1, BATCH*NH); 256 threads = warps wm(0..3) x wn(0..1)
__global__ void __launch_bounds__(256, 2)
fused_pv(const __half* __restrict__ qkv, const float* __restrict__ invZ,
         float* __restrict__ outp, __half* __restrict__ outph)
{
    extern __shared__ __half sm[];
    __half* qs = sm;                        // [2][64][QROW]  (d rows, n cols)
    __half* vs = sm + 2*64*QROW;            // [2][64][QROW]
    __half* ks = vs + 2*64*QROW;            // [64][KROW]     (d rows, m cols)

    int z = blockIdx.z;
    int b = z / NH, h = z % NH;
    const __half* qg = qkv + ((long)b*C3 +      h*DK)*HW_N;
    const __half* kg = qkv + ((long)b*C3 + CH + h*DK)*HW_N;
    const __half* vg = qkv + ((long)b*C3 + C2 + h*DK)*HW_N;
    const float*  iZ = invZ + (long)z*HW_N;
    float*  og  = outp + ((long)b*CH + h*DK)*HW_N;
    __half* ogh = outph ? outph + ((long)b*CH + h*DK)*HW_N : nullptr;
    int m0 = blockIdx.x*PVM;

    int t = threadIdx.x, warp = t >> 5, lane = t & 31;
    int g = lane >> 2, t4 = lane & 3;
    int wm = warp >> 1, wn = warp & 1;      // 4 m-tiles x 2 n-halves

    auto issue_k = [&](){
        #pragma unroll
        for (int i = 0; i < 2; i++){
            int idx = t + 256*i;            // 512 chunks (64 x 64)
            int row = idx >> 3, c8 = idx & 7;
            cpa16(smaddr(&ks[row*KROW + c8*8]), &kg[(long)row*HW_N + m0 + c8*8]);
        }
    };
    auto issue_qv = [&](int s, int n0){
        #pragma unroll
        for (int i = 0; i < 4; i++){
            int idx = t + 256*i;            // 1024 chunks (64 x 128)
            int row = idx >> 4, c16 = idx & 15;
            cpa16(smaddr(&qs[(s*64 + row)*QROW + c16*8]), &qg[(long)row*HW_N + n0 + c16*8]);
        }
        #pragma unroll
        for (int i = 0; i < 4; i++){
            int idx = t + 256*i;
            int row = idx >> 4, c16 = idx & 15;
            cpa16(smaddr(&vs[(s*64 + row)*QROW + c16*8]), &vg[(long)row*HW_N + n0 + c16*8]);
        }
        cpa_commit();
    };

    float accO[8][4] = {};                  // out^T: m16(wm) x d64 (8 d-tiles)

    issue_k();
    issue_qv(0, 0);

    for (int ch = 0; ch < NCH; ch++){
        int s = ch & 1;
        cpa_wait<0>();
        __syncthreads();
        if (ch + 1 < NCH) issue_qv(s ^ 1, (ch+1)*PVN);

        // ---- mma1: S^T[m(16,wm)][n(64,wn half)] = k^T[m][d] @ q[d][n] ----
        float sacc[8][4] = {};
        #pragma unroll
        for (int kc = 0; kc < 4; kc++){
            uint32_t a0,a1,a2,a3;
            {   // A = k as [d][m], TRA path (ldmatrix.trans + swap)
                uint32_t r0,r1,r2,r3;
                uint32_t a = smaddr(&ks[(kc*16 + (lane & 15))*KROW
                                        + wm*16 + ((lane >> 4) << 3)]);
                ldm_x4t(r0, r1, r2, r3, a);
                a0=r0; a1=r2; a2=r1; a3=r3;
            }
            #pragma unroll
            for (int nf2 = 0; nf2 < 4; nf2++){
                uint32_t b0a,b0b,b1a,b1b;
                uint32_t a = smaddr(&qs[(s*64 + kc*16 + (lane & 15))*QROW
                                        + wn*64 + nf2*16 + ((lane >> 4) << 3)]);
                ldm_x4t(b0a, b0b, b1a, b1b, a);
                mma_f16(sacc[nf2*2    ], a0, a1, a2, a3, b0a, b0b);
                mma_f16(sacc[nf2*2 + 1], a0, a1, a2, a3, b1a, b1b);
            }
        }

        // ---- exp + invZ in registers; pack C-frags as A-frags for mma2 ----
        uint32_t ha[4][4];                  // 4 k-tiles of 16 n
        #pragma unroll
        for (int j = 0; j < 4; j++){
            const float2 izA = *reinterpret_cast<const float2*>(
                &iZ[ch*PVN + wn*64 + (2*j)*8 + t4*2]);
            const float2 izB = *reinterpret_cast<const float2*>(
                &iZ[ch*PVN + wn*64 + (2*j+1)*8 + t4*2]);
            float e0 = exp2_fast(sacc[2*j][0]*ESC)*izA.x;
            float e1 = exp2_fast(sacc[2*j][1]*ESC)*izA.y;
            float e2 = exp2_fast(sacc[2*j][2]*ESC)*izA.x;
            float e3 = exp2_fast(sacc[2*j][3]*ESC)*izA.y;
            ha[j][0] = h2pack(e0, e1);
            ha[j][1] = h2pack(e2, e3);
            e0 = exp2_fast(sacc[2*j+1][0]*ESC)*izB.x;
            e1 = exp2_fast(sacc[2*j+1][1]*ESC)*izB.y;
            e2 = exp2_fast(sacc[2*j+1][2]*ESC)*izB.x;
            e3 = exp2_fast(sacc[2*j+1][3]*ESC)*izB.y;
            ha[j][2] = h2pack(e0, e1);
            ha[j][3] = h2pack(e2, e3);
        }

        // ---- mma2: accO[m16][d64] += E^T(k=n16 per kk) @ v-as-B ----
        #pragma unroll
        for (int kk = 0; kk < 4; kk++){
            #pragma unroll
            for (int dd = 0; dd < 4; dd++){
                uint32_t r0,r1,r2,r3;       // v tile [d][n], non-trans ldmatrix
                uint32_t a = smaddr(&vs[(s*64 + dd*16 + (lane & 15))*QROW
                                        + wn*64 + kk*16 + ((lane >> 4) << 3)]);
                ldm_x4(r0, r1, r2, r3, a);
                mma_f16(accO[dd*2    ], ha[kk][0], ha[kk][1], ha[kk][2], ha[kk][3], r0, r2);
                mma_f16(accO[dd*2 + 1], ha[kk][0], ha[kk][1], ha[kk][2], ha[kk][3], r1, r3);
            }
        }
    }

    // ---- reduce wn partials via smem staging, store coalesced ----
    __syncthreads();                        // all reads of q/v stages done
    float* stg = (float*)qs;                // [2][64 m][65] floats = 33280 B (fits in qs)
    #pragma unroll
    for (int df = 0; df < 8; df++){
        int base = wn*64*65 + (wm*16 + g)*65 + df*8 + t4*2;
        stg[base     ] = accO[df][0];
        stg[base + 1 ] = accO[df][1];
        stg[base + 8*65] = accO[df][2];     // row g+8
        stg[base + 8*65 + 1] = accO[df][3];
    }
    __syncthreads();
    #pragma unroll
    for (int it = 0; it < 16; it++){
        int idx = it*256 + t;
        int d = idx >> 6, mcol = idx & 63;
        float vsum = stg[mcol*65 + d] + stg[64*65 + mcol*65 + d];
        og[(long)d*HW_N + m0 + mcol] = vsum;
        if (ogh) ogh[(long)d*HW_N + m0 + mcol] = __float2half_rn(vsum);
    }
}

// ---------------- gating: channel-split partial dot products ----------------
__global__ void gate_part(const float* __restrict__ gw)
{
    int i = blockIdx.x*256 + threadIdx.x;    // over BATCH*HW_N
    int b = i / HW_N, m = i % HW_N;
    int c0 = blockIdx.y*32;
    const float* xb = g_x2 + (long)b*CH*HW_N + m;
    const float* yb = g_y2 + (long)b*CH*HW_N + m;
    float s0 = 0.f, s1 = 0.f;
    #pragma unroll 8
    for (int c = c0; c < c0+32; c++){
        float xv = xb[(long)c*HW_N];
        s0 = fmaf(gw[c],      xv, s0);
        s1 = fmaf(gw[C2 + c], xv, s1);
    }
    #pragma unroll 8
    for (int c = c0; c < c0+32; c++){
        float yv = yb[(long)c*HW_N];
        s0 = fmaf(gw[CH + c],      yv, s0);
        s1 = fmaf(gw[C2 + CH + c], yv, s1);
    }
    atomicAdd(&g_gacc[b*2*HW_N + m],        s0);
    atomicAdd(&g_gacc[b*2*HW_N + HW_N + m], s1);
}

// ---------------- final gated writeback (sigmoid inline) ----------------
__global__ void final_kernel(float* __restrict__ out, const float* __restrict__ gb)
{
    long i = (long)blockIdx.x*blockDim.x + threadIdx.x;
    if (i >= (long)BATCH*CH*HW_N) return;
    int b = (int)(i / (CH*HW_N));
    int m = (int)(i % HW_N);
    float g0 = 1.f + sigmoidf_(g_gacc[b*2*HW_N + m]        + gb[0]);
    float g1 = 1.f + sigmoidf_(g_gacc[b*2*HW_N + HW_N + m] + gb[1]);
    out[i]                       = g_x2[i] * g0;
    out[(long)BATCH*CH*HW_N + i] = g_y2[i] * g1;
}

// ---------------- host orchestration ----------------
extern "C" void kernel_launch(void* const* d_in, const int* in_sizes, int n_in,
                              void* d_out, int out_size)
{
    const float* x      = (const float*)d_in[0];
    const float* y      = (const float*)d_in[1];
    const float* fc1w   = (const float*)d_in[2];
    const float* fc1b   = (const float*)d_in[3];
    const float* fc2w   = (const float*)d_in[4];
    const float* fc2b   = (const float*)d_in[5];
    const float* t1_qw  = (const float*)d_in[6];
    const float* t1_qb  = (const float*)d_in[7];
    const float* t1_kw  = (const float*)d_in[8];
    const float* t1_kb  = (const float*)d_in[9];
    const float* t1_vw  = (const float*)d_in[10];
    const float* t1_vb  = (const float*)d_in[11];
    const float* t2_qw  = (const float*)d_in[12];
    const float* t2_qb  = (const float*)d_in[13];
    const float* t2_kw  = (const float*)d_in[14];
    const float* t2_kb  = (const float*)d_in[15];
    const float* t2_vw  = (const float*)d_in[16];
    const float* t2_vb  = (const float*)d_in[17];
    const float* gate_w = (const float*)d_in[18];
    const float* gate_b = (const float*)d_in[19];

    float *x2, *y2, *qkvb1, *qkvb2, *Zpart, *Z;
    __half *xs, *ys, *qkv, *x2h, *wqkv1, *wqkv2;
    cudaGetSymbolAddress((void**)&xs,    g_xs);
    cudaGetSymbolAddress((void**)&ys,    g_ys);
    cudaGetSymbolAddress((void**)&qkv,   g_qkv);
    cudaGetSymbolAddress((void**)&x2,    g_x2);
    cudaGetSymbolAddress((void**)&y2,    g_y2);
    cudaGetSymbolAddress((void**)&x2h,   g_x2h);
    cudaGetSymbolAddress((void**)&wqkv1, g_wqkv1);
    cudaGetSymbolAddress((void**)&wqkv2, g_wqkv2);
    cudaGetSymbolAddress((void**)&qkvb1, g_qkvb1);
    cudaGetSymbolAddress((void**)&qkvb2, g_qkvb2);
    cudaGetSymbolAddress((void**)&Zpart, g_Zpart);
    cudaGetSymbolAddress((void**)&Z,     g_Z);

    cudaFuncSetAttribute(fused_pv, cudaFuncAttributeMaxDynamicSharedMemorySize, PV_SMEM);

    const long total = (long)BATCH*CH*HW_N;
    const long long NN   = (long long)HW_N*HW_N;
    const long long CN   = (long long)CH*HW_N;
    const long long HN   = (long long)DK*HW_N;
    const long long C3N  = (long long)C3*HW_N;

    // --- prologue (slot 4 = merged qkv-conv for ncu) ---
    prep_kernel<<<1537 + BATCH*C2, 256>>>(x, y,
        t1_qw, t1_kw, t1_vw, t1_qb, t1_kb, t1_vb,
        t2_qw, t2_kw, t2_vw, t2_qb, t2_kb, t2_vb);                      // 1
    se_kernel<<<BATCH, C2>>>(fc1w, fc1b, fc2w, fc2b);                   // 2
    scale_kernel<<<(int)((total + 255)/256), 256>>>(x, y);              // 3

    auto rtrans = [&](const __half* qin, const __half* kvin,
                      const __half* wqkv, const float* qkvb,
                      float* outp, __half* outph)
    {
        // merged conv: qkv[b][o][n] = sum_c w[o][c]*in_sel[b][c][n] + b[o]
        //   BM=64/BN=64: 864 blocks (~6/SM); rows<256 (blockIdx.y<4) read qin
        hgemm<32,3, 64,64,16,32, false,1,false,false,true,4>
            <<<dim3(HW_N/64, C3/64, BATCH), 256>>>(
            wqkv, kvin, qin, qkv, qkvb, nullptr,
            CH, CH, HW_N, HW_N,
            1, 0, 0, CN, 0, C3N, 0);
        // scoresZ: row sums only (no E store); BN=64 -> 5184 blocks
        hgemm<64,1, 128,64,32,32, true,0,true,false,false,0>
            <<<dim3(HW_N/64, HW_N/128, BATCH*NH), 256>>>(
            qkv, qkv + (long)CH*HW_N, nullptr, nullptr, nullptr, Zpart,
            DK, HW_N, HW_N, HW_N,
            NH, C3N, HN, C3N, HN,
            (long long)NH*NN, NN);
        zinv_kernel<<<(BATCH*NH*HW_N + 255)/256, 256>>>();
        // fused recompute-S^T + PV (FA2-style, no Es smem bounce)
        fused_pv<<<dim3(HW_N/PVM, 1, BATCH*NH), 256, PV_SMEM>>>(
            qkv, Z, outp, outph);
    };

    // RTrans 1: x = attn(q=xs, k=ys, v=ys)
    rtrans(xs, ys, wqkv1, qkvb1, x2, x2h);
    // RTrans 2: y = attn(q=ys, k=x2, v=x2)
    rtrans(ys, x2h, wqkv2, qkvb2, y2, nullptr);

    // --- RGating + final writeback ---
    gate_part<<<dim3((BATCH*HW_N)/256, CH/32), 256>>>(gate_w);
    final_kernel<<<(int)((total + 255)/256), 256>>>((float*)d_out, gate_b);
}

// round 17
// speedup vs baseline: 1.0118x; 1.0118x over previous
#include <cuda_runtime.h>
#include <cuda_fp16.h>
#include <math.h>
#include <stdint.h>

// ---------------- problem constants ----------------
#define BATCH 2
#define CH    256
#define NH    4
#define DK    64          // CH / NH
#define HW_N  2304        // 48*48
#define C2    512         // 2*CH
#define C3    768         // 3*CH (q,k,v packed)
#define ZPARTS 72         // per-(m-tile, column-warp) partials

#define ESC 0.18033688011112042f   // 0.125 * log2(e)

// fused PV tile constants: m-tile 64, n-chunk 128, FA2-style register reuse
#define PVM 64
#define PVN 128
#define NCH (HW_N/PVN)    // 18
#define QROW 136          // q/v row stride (128 + 8 halves)
#define KROW 72           // k row stride (64 + 8 halves)
#define PV_SMEM ((2*64*QROW + 2*64*QROW + 64*KROW)*2)  // 78848 B

// ---------------- scratch (device globals) ----------
__device__ __half g_xs[BATCH*CH*HW_N];
__device__ __half g_ys[BATCH*CH*HW_N];
__device__ __half g_qkv[BATCH*C3*HW_N];           // rows 0-255 q, 256-511 k, 512-767 v  [b][c][n]
__device__ float  g_x2[BATCH*CH*HW_N];
__device__ float  g_y2[BATCH*CH*HW_N];
__device__ __half g_x2h[BATCH*CH*HW_N];
__device__ float  g_Z [BATCH*NH*HW_N];            // invZ
__device__ float  g_Zpart[ZPARTS*BATCH*NH*HW_N];  // per-(mtile,wx) partial row sums
__device__ __half g_wqkv1[C3*CH];
__device__ __half g_wqkv2[C3*CH];
__device__ float  g_qkvb1[C3];
__device__ float  g_qkvb2[C3];
__device__ float  g_pooled[BATCH*C2];
__device__ float  g_sescale[BATCH*C2];            // 1 + sigmoid(f)
__device__ float  g_gacc[BATCH*2*HW_N];           // gate pre-sigmoid accumulators

__device__ __forceinline__ float sigmoidf_(float v){ return 1.f/(1.f+expf(-v)); }

__device__ __forceinline__ float exp2_fast(float x)
{
    x = fminf(fmaxf(x, -60.f), 60.f);
    float m  = x + 12582912.0f;
    float rn = m - 12582912.0f;
    float r  = x - rn;
    int   iv = __float_as_int(m) - 0x4B400000;
    float p  = 0.0096181291f;
    p = fmaf(p, r, 0.0555041086f);
    p = fmaf(p, r, 0.2402265069f);
    p = fmaf(p, r, 0.6931471806f);
    p = fmaf(p, r, 1.0f);
    return p * __int_as_float((iv + 127) << 23);
}

__device__ __forceinline__ uint32_t smaddr(const void* p){
    return (uint32_t)__cvta_generic_to_shared(p);
}
__device__ __forceinline__ void cpa16(uint32_t dst, const void* src){
    asm volatile("cp.async.cg.shared.global [%0], [%1], 16;" :: "r"(dst), "l"(src));
}
__device__ __forceinline__ void cpa_commit(){
    asm volatile("cp.async.commit_group;" ::: "memory");
}
template<int N>
__device__ __forceinline__ void cpa_wait(){
    asm volatile("cp.async.wait_group %0;" :: "n"(N) : "memory");
}
__device__ __forceinline__ void ldm_x4(uint32_t &r0, uint32_t &r1, uint32_t &r2, uint32_t &r3,
                                       uint32_t a){
    asm volatile("ldmatrix.sync.aligned.m8n8.x4.shared.b16 {%0,%1,%2,%3}, [%4];"
        : "=r"(r0),"=r"(r1),"=r"(r2),"=r"(r3) : "r"(a));
}
__device__ __forceinline__ void ldm_x4t(uint32_t &r0, uint32_t &r1, uint32_t &r2, uint32_t &r3,
                                        uint32_t a){
    asm volatile("ldmatrix.sync.aligned.m8n8.x4.trans.shared.b16 {%0,%1,%2,%3}, [%4];"
        : "=r"(r0),"=r"(r1),"=r"(r2),"=r"(r3) : "r"(a));
}
__device__ __forceinline__ void mma_f16(float (&c)[4], uint32_t a0, uint32_t a1,
                                        uint32_t a2, uint32_t a3,
                                        uint32_t b0, uint32_t b1)
{
    asm volatile("mma.sync.aligned.m16n8k16.row.col.f32.f16.f16.f32 "
        "{%0,%1,%2,%3}, {%4,%5,%6,%7}, {%8,%9}, {%0,%1,%2,%3};"
        : "+f"(c[0]), "+f"(c[1]), "+f"(c[2]), "+f"(c[3])
        : "r"(a0), "r"(a1), "r"(a2), "r"(a3), "r"(b0), "r"(b1));
}
__device__ __forceinline__ uint32_t h2pack(float a, float b){
    __half2 h = __floats2half2_rn(a, b);
    return *reinterpret_cast<uint32_t*>(&h);
}

// ---- prep: qkv weight/bias pack (both rtrans) + gacc zero + channel pooling ----
__global__ void prep_kernel(const float* __restrict__ x, const float* __restrict__ y,
                            const float* __restrict__ qw1, const float* __restrict__ kw1,
                            const float* __restrict__ vw1,
                            const float* __restrict__ qb1, const float* __restrict__ kb1,
                            const float* __restrict__ vb1,
                            const float* __restrict__ qw2, const float* __restrict__ kw2,
                            const float* __restrict__ vw2,
                            const float* __restrict__ qb2, const float* __restrict__ kb2,
                            const float* __restrict__ vb2)
{
    int bid = blockIdx.x, t = threadIdx.x;
    if (bid < 1536){                                 // qkv weight pack: 2*768*256 elems
        int idx = bid*256 + t;
        int which = idx / (C3*CH);
        int li = idx % (C3*CH);
        int row = li / CH, col = li % CH;
        const float* w;
        int lr;
        if (row < CH)      { w = which ? qw2 : qw1; lr = row; }
        else if (row < C2) { w = which ? kw2 : kw1; lr = row - CH; }
        else               { w = which ? vw2 : vw1; lr = row - C2; }
        __half* dst = which ? g_wqkv2 : g_wqkv1;
        dst[li] = __float2half_rn(w[lr*CH + col]);
        if (li < C3){
            const float* bsrc;
            int br;
            if (li < CH)      { bsrc = which ? qb2 : qb1; br = li; }
            else if (li < C2) { bsrc = which ? kb2 : kb1; br = li - CH; }
            else              { bsrc = which ? vb2 : vb1; br = li - C2; }
            float* db = which ? g_qkvb2 : g_qkvb1;
            db[li] = bsrc[br];
        }
    } else if (bid == 1536){                         // zero gate accumulators
        for (int j = t; j < BATCH*2*HW_N; j += 256) g_gacc[j] = 0.f;
    } else {                                         // channel-mean pooling
        int idx = bid - 1537;                        // over BATCH*C2
        int b = idx / C2, ch = idx % C2;
        const float* src = (ch < CH) ? (x + ((long)b*CH + ch)*HW_N)
                                     : (y + ((long)b*CH + (ch-CH))*HW_N);
        float s = 0.f;
        for (int i = t; i < HW_N; i += 256) s += src[i];
        __shared__ float red[256];
        red[t] = s; __syncthreads();
        for (int st = 128; st > 0; st >>= 1){
            if (t < st) red[t] += red[t+st];
            __syncthreads();
        }
        if (t == 0) g_pooled[idx] = red[0] / (float)HW_N;
    }
}

// ---------------- SE MLP (tiny, 2 blocks) ----------------
__global__ void se_kernel(const float* __restrict__ w1, const float* __restrict__ b1,
                          const float* __restrict__ w2, const float* __restrict__ b2)
{
    int b = blockIdx.x, t = threadIdx.x;   // 512 threads
    __shared__ float sp[C2], sh[DK];
    sp[t] = g_pooled[b*C2 + t];
    __syncthreads();
    if (t < DK) {
        float s = b1[t];
        for (int c = 0; c < C2; c++) s += w1[t*C2 + c] * sp[c];
        sh[t] = fmaxf(s, 0.f);
    }
    __syncthreads();
    float f = b2[t];
    for (int j = 0; j < DK; j++) f += w2[t*DK + j] * sh[j];
    g_sescale[b*C2 + t] = 1.f + sigmoidf_(f);
}

// ---------------- elementwise SE scale (coalesced) ----------------
__global__ void scale_kernel(const float* __restrict__ x, const float* __restrict__ y)
{
    long i = (long)blockIdx.x*blockDim.x + threadIdx.x;
    if (i >= (long)BATCH*CH*HW_N) return;
    int b = (int)(i / (CH*HW_N));
    int c = (int)((i / HW_N) % CH);
    g_xs[i] = __float2half_rn(x[i] * g_sescale[b*C2 + c]);
    g_ys[i] = __float2half_rn(y[i] * g_sescale[b*C2 + CH + c]);
}

// invZ from ZPARTS partials
__global__ void zinv_kernel()
{
    int i = blockIdx.x*blockDim.x + threadIdx.x;
    if (i >= BATCH*NH*HW_N) return;
    float s = 0.f;
    #pragma unroll
    for (int p = 0; p < ZPARTS; p++) s += g_Zpart[(long)p*(BATCH*NH*HW_N) + i];
    g_Z[i] = 1.0f / s;
}

// ================= all-half cp.async tensor-core GEMM =================
// QLIM>0: B operand = (blockIdx.y < QLIM) ? Bq : B  (merged qkv conv)
// EXPZ: compute exp rowsums -> Zpart; ESTORE controls whether E is written
template<int BK, int ST, int BM, int BN, int WM, int WN,
         bool TRA, int BIAS, bool EXPZ, bool ESTORE, bool CHALF, int QLIM>
__global__ void __launch_bounds__(256)
hgemm(const __half* __restrict__ A, const __half* __restrict__ B,
      const __half* __restrict__ Bq,
      void* __restrict__ Cv,
      const float* __restrict__ bias, float* __restrict__ Zp,
      int K, int lda, int ldb, int ldc, int zdiv,
      long long sA1, long long sA2, long long sB1, long long sB2,
      long long sC1, long long sC2)
{
    constexpr int WCOLS = BN / WN;
    constexpr int MF = WM / 16;
    constexpr int NF = WN / 8;
    constexpr int PAD = 8;
    constexpr int A_CH = (BM*BK/8)/256;
    constexpr int B_CH = (BK*BN/8)/256;

    __shared__ __half As[ST][TRA ? BK : BM][(TRA ? BM : BK) + PAD];
    __shared__ __half Bs[ST][BK][BN + PAD];

    int z  = blockIdx.z;
    int z1 = z / zdiv, z2 = z - z1*zdiv;
    A += z1*sA1 + z2*sA2;
    if (QLIM > 0 && blockIdx.y < QLIM) B = Bq;
    B += z1*sB1 + z2*sB2;
    float*  Cf = CHALF ? nullptr : ((float*)Cv ? (float*)Cv + z1*sC1 + z2*sC2 : nullptr);
    __half* Ch = CHALF ? ((__half*)Cv + z1*sC1 + z2*sC2)
                       : ((EXPZ && ESTORE) ? ((__half*)Cv + z1*sC1 + z2*sC2) : nullptr);

    int bm = blockIdx.y*BM, bn = blockIdx.x*BN;

    int t    = threadIdx.x;
    int warp = t >> 5, lane = t & 31;
    int g = lane >> 2, t4 = lane & 3;
    int wy = warp / WCOLS, wx = warp % WCOLS;

    auto issue = [&](int s, int k0){
        #pragma unroll
        for (int i = 0; i < A_CH; i++){
            int idx = t + 256*i;
            if (TRA){
                int k = idx/(BM/8), m8 = idx%(BM/8);
                cpa16(smaddr(&As[s][k][m8*8]), &A[(long)(k0+k)*lda + bm + m8*8]);
            } else {
                int m = idx/(BK/8), k8 = idx%(BK/8);
                cpa16(smaddr(&As[s][m][k8*8]), &A[(long)(bm+m)*lda + k0 + k8*8]);
            }
        }
        #pragma unroll
        for (int i = 0; i < B_CH; i++){
            int idx = t + 256*i;
            int k = idx/(BN/8), n8 = idx%(BN/8);
            cpa16(smaddr(&Bs[s][k][n8*8]), &B[(long)(k0+k)*ldb + bn + n8*8]);
        }
        cpa_commit();
    };

    float acc[MF][NF][4] = {};

    int nT = K / BK;
    constexpr int PRE = (ST == 1) ? 1 : (ST - 1);
    #pragma unroll
    for (int s = 0; s < PRE; s++)
        if (s < nT) issue(s, s*BK);

    for (int tI = 0; tI < nT; tI++){
        if (ST >= 3 && tI < nT - (ST-2)) cpa_wait<(ST >= 3) ? ST-2 : 0>();
        else                             cpa_wait<0>();
        __syncthreads();
        if (ST > 1 && tI + ST-1 < nT) issue((tI + ST-1) % ST, (tI + ST-1)*BK);

        int cur = tI % ST;
        #pragma unroll
        for (int kc = 0; kc < BK/16; kc++){
            uint32_t af[MF][4]; uint32_t bf[NF][2];
            #pragma unroll
            for (int mf = 0; mf < MF; mf++){
                if (TRA){
                    uint32_t r0,r1,r2,r3;
                    uint32_t a = smaddr(&As[cur][kc*16 + (lane & 15)]
                                                [wy*WM + mf*16 + ((lane >> 4) << 3)]);
                    ldm_x4t(r0, r1, r2, r3, a);
                    af[mf][0]=r0; af[mf][1]=r2; af[mf][2]=r1; af[mf][3]=r3;
                } else {
                    uint32_t a = smaddr(&As[cur][wy*WM + mf*16 + (lane & 15)]
                                                [kc*16 + ((lane >> 4) << 3)]);
                    ldm_x4(af[mf][0], af[mf][1], af[mf][2], af[mf][3], a);
                }
            }
            #pragma unroll
            for (int nf2 = 0; nf2 < NF/2; nf2++){
                uint32_t a = smaddr(&Bs[cur][kc*16 + (lane & 15)]
                                            [wx*WN + nf2*16 + ((lane >> 4) << 3)]);
                ldm_x4t(bf[nf2*2][0], bf[nf2*2][1], bf[nf2*2+1][0], bf[nf2*2+1][1], a);
            }
            #pragma unroll
            for (int mf = 0; mf < MF; mf++)
                #pragma unroll
                for (int nf = 0; nf < NF; nf++)
                    mma_f16(acc[mf][nf], af[mf][0], af[mf][1], af[mf][2], af[mf][3],
                            bf[nf][0], bf[nf][1]);
        }
    }

    // ---------------- epilogue ----------------
    #pragma unroll
    for (int mf = 0; mf < MF; mf++){
        int rbase = bm + wy*WM + mf*16 + g;
        #pragma unroll
        for (int half = 0; half < 2; half++){
            int r = rbase + half*8;
            float bM = (BIAS == 1) ? bias[r] : 0.f;
            float rowsum = 0.f;
            #pragma unroll
            for (int nf = 0; nf < NF; nf++){
                int cI = bn + wx*WN + nf*8 + t4*2;
                float v0 = acc[mf][nf][half*2 + 0];
                float v1 = acc[mf][nf][half*2 + 1];
                if (EXPZ){
                    v0 = exp2_fast(v0*ESC);
                    v1 = exp2_fast(v1*ESC);
                    rowsum += v0 + v1;
                    if (ESTORE)
                        *reinterpret_cast<__half2*>(&Ch[(long)r*ldc + cI]) =
                            __floats2half2_rn(v0, v1);
                } else {
                    if (BIAS == 1){ v0 += bM; v1 += bM; }
                    if (CHALF){
                        *reinterpret_cast<__half2*>(&Ch[(long)r*ldc + cI]) =
                            __floats2half2_rn(v0, v1);
                    } else {
                        *reinterpret_cast<float2*>(&Cf[(long)r*ldc + cI]) = make_float2(v0, v1);
                    }
                }
            }
            if (EXPZ){
                rowsum += __shfl_xor_sync(0xffffffffu, rowsum, 1);
                rowsum += __shfl_xor_sync(0xffffffffu, rowsum, 2);
                if (t4 == 0)
                    Zp[((long)(blockIdx.x*WCOLS + wx)*(BATCH*NH) + z)*HW_N + r] = rowsum;
            }
        }
    }
}

// ========== fused recompute-S^T + PV, FA2-style register reuse ==========
// out^T[m][d] = sum_n E^T[m][n] * v^T[n][d];  E^T = exp2(S^T*ESC)*invZ[n]
// grid: (HW_N/PVM, 1, BATCH*NH); 256 threads = warps wm(0..3) x wn(0..1)
__global__ void __launch_bounds__(256, 2)
fused_pv(const __half* __restrict__ qkv, const float* __restrict__ invZ,
         float* __restrict__ outp, __half* __restrict__ outph)
{
    extern __shared__ __half sm[];
    __half* qs = sm;                        // [2][64][QROW]  (d rows, n cols)
    __half* vs = sm + 2*64*QROW;            // [2][64][QROW]
    __half* ks = vs + 2*64*QROW;            // [64][KROW]     (d rows, m cols)

    int z = blockIdx.z;
    int b = z / NH, h = z % NH;
    const __half* qg = qkv + ((long)b*C3 +      h*DK)*HW_N;
    const __half* kg = qkv + ((long)b*C3 + CH + h*DK)*HW_N;
    const __half* vg = qkv + ((long)b*C3 + C2 + h*DK)*HW_N;
    const float*  iZ = invZ + (long)z*HW_N;
    float*  og  = outp + ((long)b*CH + h*DK)*HW_N;
    __half* ogh = outph ? outph + ((long)b*CH + h*DK)*HW_N : nullptr;
    int m0 = blockIdx.x*PVM;

    int t = threadIdx.x, warp = t >> 5, lane = t & 31;
    int g = lane >> 2, t4 = lane & 3;
    int wm = warp >> 1, wn = warp & 1;      // 4 m-tiles x 2 n-halves

    auto issue_k = [&](){
        #pragma unroll
        for (int i = 0; i < 2; i++){
            int idx = t + 256*i;            // 512 chunks (64 x 64)
            int row = idx >> 3, c8 = idx & 7;
            cpa16(smaddr(&ks[row*KROW + c8*8]), &kg[(long)row*HW_N + m0 + c8*8]);
        }
    };
    auto issue_qv = [&](int s, int n0){
        #pragma unroll
        for (int i = 0; i < 4; i++){
            int idx = t + 256*i;            // 1024 chunks (64 x 128)
            int row = idx >> 4, c16 = idx & 15;
            cpa16(smaddr(&qs[(s*64 + row)*QROW + c16*8]), &qg[(long)row*HW_N + n0 + c16*8]);
        }
        #pragma unroll
        for (int i = 0; i < 4; i++){
            int idx = t + 256*i;
            int row = idx >> 4, c16 = idx & 15;
            cpa16(smaddr(&vs[(s*64 + row)*QROW + c16*8]), &vg[(long)row*HW_N + n0 + c16*8]);
        }
        cpa_commit();
    };

    float accO[8][4] = {};                  // out^T: m16(wm) x d64 (8 d-tiles)

    issue_k();
    issue_qv(0, 0);

    for (int ch = 0; ch < NCH; ch++){
        int s = ch & 1;
        cpa_wait<0>();
        __syncthreads();
        if (ch + 1 < NCH) issue_qv(s ^ 1, (ch+1)*PVN);

        // ---- mma1: S^T[m(16,wm)][n(64,wn half)] = k^T[m][d] @ q[d][n] ----
        float sacc[8][4] = {};
        #pragma unroll
        for (int kc = 0; kc < 4; kc++){
            uint32_t a0,a1,a2,a3;
            {   // A = k as [d][m], TRA path (ldmatrix.trans + swap)
                uint32_t r0,r1,r2,r3;
                uint32_t a = smaddr(&ks[(kc*16 + (lane & 15))*KROW
                                        + wm*16 + ((lane >> 4) << 3)]);
                ldm_x4t(r0, r1, r2, r3, a);
                a0=r0; a1=r2; a2=r1; a3=r3;
            }
            #pragma unroll
            for (int nf2 = 0; nf2 < 4; nf2++){
                uint32_t b0a,b0b,b1a,b1b;
                uint32_t a = smaddr(&qs[(s*64 + kc*16 + (lane & 15))*QROW
                                        + wn*64 + nf2*16 + ((lane >> 4) << 3)]);
                ldm_x4t(b0a, b0b, b1a, b1b, a);
                mma_f16(sacc[nf2*2    ], a0, a1, a2, a3, b0a, b0b);
                mma_f16(sacc[nf2*2 + 1], a0, a1, a2, a3, b1a, b1b);
            }
        }

        // ---- exp + invZ in registers; pack C-frags as A-frags for mma2 ----
        uint32_t ha[4][4];                  // 4 k-tiles of 16 n
        #pragma unroll
        for (int j = 0; j < 4; j++){
            const float2 izA = *reinterpret_cast<const float2*>(
                &iZ[ch*PVN + wn*64 + (2*j)*8 + t4*2]);
            const float2 izB = *reinterpret_cast<const float2*>(
                &iZ[ch*PVN + wn*64 + (2*j+1)*8 + t4*2]);
            float e0 = exp2_fast(sacc[2*j][0]*ESC)*izA.x;
            float e1 = exp2_fast(sacc[2*j][1]*ESC)*izA.y;
            float e2 = exp2_fast(sacc[2*j][2]*ESC)*izA.x;
            float e3 = exp2_fast(sacc[2*j][3]*ESC)*izA.y;
            ha[j][0] = h2pack(e0, e1);
            ha[j][1] = h2pack(e2, e3);
            e0 = exp2_fast(sacc[2*j+1][0]*ESC)*izB.x;
            e1 = exp2_fast(sacc[2*j+1][1]*ESC)*izB.y;
            e2 = exp2_fast(sacc[2*j+1][2]*ESC)*izB.x;
            e3 = exp2_fast(sacc[2*j+1][3]*ESC)*izB.y;
            ha[j][2] = h2pack(e0, e1);
            ha[j][3] = h2pack(e2, e3);
        }

        // ---- mma2: accO[m16][d64] += E^T(k=n16 per kk) @ v-as-B ----
        #pragma unroll
        for (int kk = 0; kk < 4; kk++){
            #pragma unroll
            for (int dd = 0; dd < 4; dd++){
                uint32_t r0,r1,r2,r3;       // v tile [d][n], non-trans ldmatrix
                uint32_t a = smaddr(&vs[(s*64 + dd*16 + (lane & 15))*QROW
                                        + wn*64 + kk*16 + ((lane >> 4) << 3)]);
                ldm_x4(r0, r1, r2, r3, a);
                mma_f16(accO[dd*2    ], ha[kk][0], ha[kk][1], ha[kk][2], ha[kk][3], r0, r2);
                mma_f16(accO[dd*2 + 1], ha[kk][0], ha[kk][1], ha[kk][2], ha[kk][3], r1, r3);
            }
        }
    }

    // ---- reduce wn partials via smem staging, store coalesced ----
    __syncthreads();                        // all reads of q/v stages done
    float* stg = (float*)qs;                // [2][64 m][65] floats = 33280 B (fits in qs)
    #pragma unroll
    for (int df = 0; df < 8; df++){
        int base = wn*64*65 + (wm*16 + g)*65 + df*8 + t4*2;
        stg[base     ] = accO[df][0];
        stg[base + 1 ] = accO[df][1];
        stg[base + 8*65] = accO[df][2];     // row g+8
        stg[base + 8*65 + 1] = accO[df][3];
    }
    __syncthreads();
    #pragma unroll
    for (int it = 0; it < 16; it++){
        int idx = it*256 + t;
        int d = idx >> 6, mcol = idx & 63;
        float vsum = stg[mcol*65 + d] + stg[64*65 + mcol*65 + d];
        og[(long)d*HW_N + m0 + mcol] = vsum;
        if (ogh) ogh[(long)d*HW_N + m0 + mcol] = __float2half_rn(vsum);
    }
}

// ---------------- gating: channel-split partial dot products ----------------
__global__ void gate_part(const float* __restrict__ gw)
{
    int i = blockIdx.x*256 + threadIdx.x;    // over BATCH*HW_N
    int b = i / HW_N, m = i % HW_N;
    int c0 = blockIdx.y*32;
    const float* xb = g_x2 + (long)b*CH*HW_N + m;
    const float* yb = g_y2 + (long)b*CH*HW_N + m;
    float s0 = 0.f, s1 = 0.f;
    #pragma unroll 8
    for (int c = c0; c < c0+32; c++){
        float xv = xb[(long)c*HW_N];
        s0 = fmaf(gw[c],      xv, s0);
        s1 = fmaf(gw[C2 + c], xv, s1);
    }
    #pragma unroll 8
    for (int c = c0; c < c0+32; c++){
        float yv = yb[(long)c*HW_N];
        s0 = fmaf(gw[CH + c],      yv, s0);
        s1 = fmaf(gw[C2 + CH + c], yv, s1);
    }
    atomicAdd(&g_gacc[b*2*HW_N + m],        s0);
    atomicAdd(&g_gacc[b*2*HW_N + HW_N + m], s1);
}

// ---------------- final gated writeback (sigmoid inline) ----------------
__global__ void final_kernel(float* __restrict__ out, const float* __restrict__ gb)
{
    long i = (long)blockIdx.x*blockDim.x + threadIdx.x;
    if (i >= (long)BATCH*CH*HW_N) return;
    int b = (int)(i / (CH*HW_N));
    int m = (int)(i % HW_N);
    float g0 = 1.f + sigmoidf_(g_gacc[b*2*HW_N + m]        + gb[0]);
    float g1 = 1.f + sigmoidf_(g_gacc[b*2*HW_N + HW_N + m] + gb[1]);
    out[i]                       = g_x2[i] * g0;
    out[(long)BATCH*CH*HW_N + i] = g_y2[i] * g1;
}

// ---------------- host orchestration ----------------
extern "C" void kernel_launch(void* const* d_in, const int* in_sizes, int n_in,
                              void* d_out, int out_size)
{
    const float* x      = (const float*)d_in[0];
    const float* y      = (const float*)d_in[1];
    const float* fc1w   = (const float*)d_in[2];
    const float* fc1b   = (const float*)d_in[3];
    const float* fc2w   = (const float*)d_in[4];
    const float* fc2b   = (const float*)d_in[5];
    const float* t1_qw  = (const float*)d_in[6];
    const float* t1_qb  = (const float*)d_in[7];
    const float* t1_kw  = (const float*)d_in[8];
    const float* t1_kb  = (const float*)d_in[9];
    const float* t1_vw  = (const float*)d_in[10];
    const float* t1_vb  = (const float*)d_in[11];
    const float* t2_qw  = (const float*)d_in[12];
    const float* t2_qb  = (const float*)d_in[13];
    const float* t2_kw  = (const float*)d_in[14];
    const float* t2_kb  = (const float*)d_in[15];
    const float* t2_vw  = (const float*)d_in[16];
    const float* t2_vb  = (const float*)d_in[17];
    const float* gate_w = (const float*)d_in[18];
    const float* gate_b = (const float*)d_in[19];

    float *x2, *y2, *qkvb1, *qkvb2, *Zpart, *Z;
    __half *xs, *ys, *qkv, *x2h, *wqkv1, *wqkv2;
    cudaGetSymbolAddress((void**)&xs,    g_xs);
    cudaGetSymbolAddress((void**)&ys,    g_ys);
    cudaGetSymbolAddress((void**)&qkv,   g_qkv);
    cudaGetSymbolAddress((void**)&x2,    g_x2);
    cudaGetSymbolAddress((void**)&y2,    g_y2);
    cudaGetSymbolAddress((void**)&x2h,   g_x2h);
    cudaGetSymbolAddress((void**)&wqkv1, g_wqkv1);
    cudaGetSymbolAddress((void**)&wqkv2, g_wqkv2);
    cudaGetSymbolAddress((void**)&qkvb1, g_qkvb1);
    cudaGetSymbolAddress((void**)&qkvb2, g_qkvb2);
    cudaGetSymbolAddress((void**)&Zpart, g_Zpart);
    cudaGetSymbolAddress((void**)&Z,     g_Z);

    cudaFuncSetAttribute(fused_pv, cudaFuncAttributeMaxDynamicSharedMemorySize, PV_SMEM);

    const long total = (long)BATCH*CH*HW_N;
    const long long NN   = (long long)HW_N*HW_N;
    const long long CN   = (long long)CH*HW_N;
    const long long HN   = (long long)DK*HW_N;
    const long long C3N  = (long long)C3*HW_N;

    // --- prologue (slot 4 = merged qkv-conv for ncu) ---
    prep_kernel<<<1537 + BATCH*C2, 256>>>(x, y,
        t1_qw, t1_kw, t1_vw, t1_qb, t1_kb, t1_vb,
        t2_qw, t2_kw, t2_vw, t2_qb, t2_kb, t2_vb);                      // 1
    se_kernel<<<BATCH, C2>>>(fc1w, fc1b, fc2w, fc2b);                   // 2
    scale_kernel<<<(int)((total + 255)/256), 256>>>(x, y);              // 3

    auto rtrans = [&](const __half* qin, const __half* kvin,
                      const __half* wqkv, const float* qkvb,
                      float* outp, __half* outph)
    {
        // merged conv: qkv[b][o][n] = sum_c w[o][c]*in_sel[b][c][n] + b[o]
        //   BM=64/BN=128 (R15 best): 432 blocks; rows<256 (blockIdx.y<4) read qin
        hgemm<32,3, 64,128,32,32, false,1,false,false,true,4>
            <<<dim3(HW_N/128, C3/64, BATCH), 256>>>(
            wqkv, kvin, qin, qkv, qkvb, nullptr,
            CH, CH, HW_N, HW_N,
            1, 0, 0, CN, 0, C3N, 0);
        // scoresZ: row sums only (no E store); BN=64 -> 5184 blocks
        hgemm<64,1, 128,64,32,32, true,0,true,false,false,0>
            <<<dim3(HW_N/64, HW_N/128, BATCH*NH), 256>>>(
            qkv, qkv + (long)CH*HW_N, nullptr, nullptr, nullptr, Zpart,
            DK, HW_N, HW_N, HW_N,
            NH, C3N, HN, C3N, HN,
            (long long)NH*NN, NN);
        zinv_kernel<<<(BATCH*NH*HW_N + 255)/256, 256>>>();
        // fused recompute-S^T + PV (FA2-style, no Es smem bounce)
        fused_pv<<<dim3(HW_N/PVM, 1, BATCH*NH), 256, PV_SMEM>>>(
            qkv, Z, outp, outph);
    };

    // RTrans 1: x = attn(q=xs, k=ys, v=ys)
    rtrans(xs, ys, wqkv1, qkvb1, x2, x2h);
    // RTrans 2: y = attn(q=ys, k=x2, v=x2)
    rtrans(ys, x2h, wqkv2, qkvb2, y2, nullptr);

    // --- RGating + final writeback ---
    gate_part<<<dim3((BATCH*HW_N)/256, CH/32), 256>>>(gate_w);
    final_kernel<<<(int)((total + 255)/256), 256>>>((float*)d_out, gate_b);
}